// round 1
// baseline (speedup 1.0000x reference)
#include <cuda_runtime.h>

#define NB 16
#define NA 128
#define HD 256
#define EF 30
#define EFP 32   // padded row stride for e tile in smem (float4-friendly)

// SELU constants
#define SELU_SCALE 1.0507009873554805f
#define SELU_SCALE_ALPHA 1.7580993408473766f   // scale * alpha

// scratch for h1 (16*128*256 fp32 = 2 MB)
__device__ float g_h1[NB * NA * HD];

__device__ __forceinline__ unsigned long long pack2(float a, float b) {
    return (unsigned long long)__float_as_uint(a) |
           ((unsigned long long)__float_as_uint(b) << 32);
}
__device__ __forceinline__ float lo32f(unsigned long long v) {
    return __uint_as_float((unsigned)(v & 0xffffffffull));
}
__device__ __forceinline__ float hi32f(unsigned long long v) {
    return __uint_as_float((unsigned)(v >> 32));
}
__device__ __forceinline__ unsigned long long fma2(unsigned long long a,
                                                   unsigned long long b,
                                                   unsigned long long c) {
    unsigned long long d;
    asm("fma.rn.f32x2 %0, %1, %2, %3;" : "=l"(d) : "l"(a), "l"(b), "l"(c));
    return d;
}
__device__ __forceinline__ unsigned long long add2(unsigned long long a,
                                                   unsigned long long b) {
    unsigned long long d;
    asm("add.rn.f32x2 %0, %1, %2;" : "=l"(d) : "l"(a), "l"(b));
    return d;
}

__device__ __forceinline__ float selu_f(float d) {
    float pos = SELU_SCALE * d;
    float neg = SELU_SCALE_ALPHA * (__expf(d) - 1.0f);
    return d > 0.0f ? pos : neg;
}

// -------------------------------------------------------------------------
// Kernel 1: fused  e_f = selu(e @ Wf^T + bf) * edge_mask ;
//                  h1[b,i,f] = sum_j e_f[b,i,j,f] * h[b,j,f]
// One block per (b,i). 256 threads, thread = f. e tile staged in smem,
// Wf row packed into f32x2 registers, dot done with fma.rn.f32x2.
// -------------------------------------------------------------------------
__global__ __launch_bounds__(256) void efconv_k1(
    const float* __restrict__ h,
    const float* __restrict__ e,
    const float* __restrict__ edge_mask,
    const float* __restrict__ Wf,
    const float* __restrict__ bf)
{
    __shared__ __align__(16) float e_sh[NA * EFP];
    __shared__ float em_sh[NA];

    const int bi = blockIdx.x;          // b*NA + i
    const int b  = bi >> 7;             // NA = 128
    const int f  = threadIdx.x;

    // stage e[b,i,:,:] (128 x 30) into padded smem rows of 32
    const float* ep = e + (size_t)bi * NA * EF;
    #pragma unroll
    for (int t = f; t < NA * EF; t += 256) {
        int j = t / EF;
        int k = t - j * EF;
        e_sh[j * EFP + k] = ep[t];
    }
    if (f < NA) em_sh[f] = edge_mask[bi * NA + f];

    // pack Wf row (30 floats -> 15 f32x2)
    unsigned long long wp[15];
    const float* wrow = Wf + f * EF;
    #pragma unroll
    for (int q = 0; q < 15; q++)
        wp[q] = pack2(wrow[2 * q], wrow[2 * q + 1]);
    const float bias = bf[f];

    const float* hb = h + (size_t)b * NA * HD + f;
    __syncthreads();

    float acc = 0.0f;
    #pragma unroll 2
    for (int j = 0; j < NA; j++) {
        const unsigned long long* row =
            (const unsigned long long*)(e_sh + j * EFP);
        // 7x float4 (pairs) + 1x float2 tail = 30 elements
        unsigned long long a0 = 0ull, a1 = 0ull, a2 = 0ull, a3 = 0ull;
        a0 = fma2(row[0],  wp[0],  a0);
        a1 = fma2(row[1],  wp[1],  a1);
        a2 = fma2(row[2],  wp[2],  a2);
        a3 = fma2(row[3],  wp[3],  a3);
        a0 = fma2(row[4],  wp[4],  a0);
        a1 = fma2(row[5],  wp[5],  a1);
        a2 = fma2(row[6],  wp[6],  a2);
        a3 = fma2(row[7],  wp[7],  a3);
        a0 = fma2(row[8],  wp[8],  a0);
        a1 = fma2(row[9],  wp[9],  a1);
        a2 = fma2(row[10], wp[10], a2);
        a3 = fma2(row[11], wp[11], a3);
        a0 = fma2(row[12], wp[12], a0);
        a1 = fma2(row[13], wp[13], a1);
        a2 = fma2(row[14], wp[14], a2);   // tail pair (k=28,29)
        a0 = add2(a0, a1);
        a2 = add2(a2, a3);
        a0 = add2(a0, a2);
        float d = (lo32f(a0) + hi32f(a0)) + bias;
        float s = selu_f(d);
        acc = fmaf(s * em_sh[j], __ldg(hb + (size_t)j * HD), acc);
    }
    g_h1[(size_t)bi * HD + f] = acc;
}

// -------------------------------------------------------------------------
// Kernel 2: node MLP GEMM  (M=2048 rows, K=512, N=256) + SELU gate + residual
// Block tile: 16 rows x 256 cols, 256 threads, thread tile 4i x 4f.
// W chunk staged transposed [c][f] (padded stride 260) for conflict-free
// float4 reads; z tile [i][c].
// -------------------------------------------------------------------------
#define K2_TI 16
#define K2_KC 32
#define K2_WPAD 260

__global__ __launch_bounds__(256) void efconv_k2(
    const float* __restrict__ h,
    const float* __restrict__ node_mask,
    const float* __restrict__ Ww,
    const float* __restrict__ bw,
    float* __restrict__ out)
{
    __shared__ __align__(16) float z_sh[K2_TI * K2_KC];       // [i][c]  2 KB
    __shared__ __align__(16) float w_sh[K2_KC * K2_WPAD];     // [c][f] 33 KB

    const int tid = threadIdx.x;
    const int r0  = blockIdx.x * K2_TI;
    const int f0  = (tid & 63) * 4;       // 0..252
    const int i0  = (tid >> 6) * 4;       // 0..12

    float4 acc[4];
    #pragma unroll
    for (int ii = 0; ii < 4; ii++) acc[ii] = make_float4(0.f, 0.f, 0.f, 0.f);

    for (int c0 = 0; c0 < 2 * HD; c0 += K2_KC) {
        // ---- stage z tile: 16 x 32 = 128 float4, first 128 threads ----
        if (tid < 128) {
            int i  = tid >> 3;
            int cq = tid & 7;
            int r  = r0 + i;
            int c  = c0 + cq * 4;
            float4 v;
            if (c < HD)
                v = *(const float4*)(h + (size_t)r * HD + c);
            else
                v = *(const float4*)(g_h1 + (size_t)r * HD + (c - HD));
            *(float4*)(z_sh + i * K2_KC + cq * 4) = v;
        }
        // ---- stage W chunk transposed: 256 f x 32 c -> w_sh[c][f] ----
        #pragma unroll
        for (int t = tid; t < 256 * 8; t += 256) {
            int fr = t >> 3;
            int cq = t & 7;
            float4 v = *(const float4*)(Ww + (size_t)fr * (2 * HD) + c0 + cq * 4);
            w_sh[(cq * 4 + 0) * K2_WPAD + fr] = v.x;
            w_sh[(cq * 4 + 1) * K2_WPAD + fr] = v.y;
            w_sh[(cq * 4 + 2) * K2_WPAD + fr] = v.z;
            w_sh[(cq * 4 + 3) * K2_WPAD + fr] = v.w;
        }
        __syncthreads();

        #pragma unroll
        for (int cq = 0; cq < 8; cq++) {
            float4 wv[4];
            #pragma unroll
            for (int cc = 0; cc < 4; cc++)
                wv[cc] = *(const float4*)(w_sh + (cq * 4 + cc) * K2_WPAD + f0);
            float4 zv[4];
            #pragma unroll
            for (int ii = 0; ii < 4; ii++)
                zv[ii] = *(const float4*)(z_sh + (i0 + ii) * K2_KC + cq * 4);
            #pragma unroll
            for (int ii = 0; ii < 4; ii++) {
                acc[ii].x = fmaf(zv[ii].x, wv[0].x, acc[ii].x);
                acc[ii].y = fmaf(zv[ii].x, wv[0].y, acc[ii].y);
                acc[ii].z = fmaf(zv[ii].x, wv[0].z, acc[ii].z);
                acc[ii].w = fmaf(zv[ii].x, wv[0].w, acc[ii].w);
                acc[ii].x = fmaf(zv[ii].y, wv[1].x, acc[ii].x);
                acc[ii].y = fmaf(zv[ii].y, wv[1].y, acc[ii].y);
                acc[ii].z = fmaf(zv[ii].y, wv[1].z, acc[ii].z);
                acc[ii].w = fmaf(zv[ii].y, wv[1].w, acc[ii].w);
                acc[ii].x = fmaf(zv[ii].z, wv[2].x, acc[ii].x);
                acc[ii].y = fmaf(zv[ii].z, wv[2].y, acc[ii].y);
                acc[ii].z = fmaf(zv[ii].z, wv[2].z, acc[ii].z);
                acc[ii].w = fmaf(zv[ii].z, wv[2].w, acc[ii].w);
                acc[ii].x = fmaf(zv[ii].w, wv[3].x, acc[ii].x);
                acc[ii].y = fmaf(zv[ii].w, wv[3].y, acc[ii].y);
                acc[ii].z = fmaf(zv[ii].w, wv[3].z, acc[ii].z);
                acc[ii].w = fmaf(zv[ii].w, wv[3].w, acc[ii].w);
            }
        }
        __syncthreads();
    }

    // ---- epilogue: selu(acc + bw) * node_mask + h ----
    float4 bwv = *(const float4*)(bw + f0);
    #pragma unroll
    for (int ii = 0; ii < 4; ii++) {
        int r = r0 + i0 + ii;
        float m = node_mask[r];
        float4 hv = *(const float4*)(h + (size_t)r * HD + f0);
        float4 o;
        o.x = selu_f(acc[ii].x + bwv.x) * m + hv.x;
        o.y = selu_f(acc[ii].y + bwv.y) * m + hv.y;
        o.z = selu_f(acc[ii].z + bwv.z) * m + hv.z;
        o.w = selu_f(acc[ii].w + bwv.w) * m + hv.w;
        *(float4*)(out + (size_t)r * HD + f0) = o;
    }
}

extern "C" void kernel_launch(void* const* d_in, const int* in_sizes, int n_in,
                              void* d_out, int out_size)
{
    const float* h   = (const float*)d_in[0];   // (16,128,256)
    const float* e   = (const float*)d_in[1];   // (16,128,128,30)
    const float* nm  = (const float*)d_in[2];   // (16,128,1)
    const float* em  = (const float*)d_in[3];   // (16,128,128,1)
    const float* Wf  = (const float*)d_in[4];   // (256,30)
    const float* bf  = (const float*)d_in[5];   // (256,)
    const float* Ww  = (const float*)d_in[6];   // (256,512)
    const float* bw  = (const float*)d_in[7];   // (256,)
    float* out = (float*)d_out;                  // (16,128,256)

    efconv_k1<<<NB * NA, 256>>>(h, e, em, Wf, bf);
    efconv_k2<<<(NB * NA) / K2_TI, 256>>>(h, nm, Ww, bw, out);
}

// round 3
// speedup vs baseline: 1.6446x; 1.6446x over previous
#include <cuda_runtime.h>
#include <cstdint>

#define NBATCH 16
#define NA 128
#define HD 256
#define EF 30

#define SELU_SCALE 1.0507009873554805f
#define SELU_SCALE_ALPHA 1.7580993408473766f

// intermediate h1 (16*128*256 fp32 = 2 MB)
__device__ float g_h1[NBATCH * NA * HD];

__device__ __forceinline__ uint32_t f2tf(float x) {
    uint32_t u; asm("cvt.rna.tf32.f32 %0, %1;" : "=r"(u) : "f"(x)); return u;
}
__device__ __forceinline__ float selu_f(float d) {
    return d > 0.f ? SELU_SCALE * d : SELU_SCALE_ALPHA * (__expf(d) - 1.f);
}
__device__ __forceinline__ void mma_tf32(float c[4],
                                         uint32_t a0, uint32_t a1, uint32_t a2, uint32_t a3,
                                         uint32_t b0, uint32_t b1) {
    asm volatile(
        "mma.sync.aligned.m16n8k8.row.col.f32.tf32.tf32.f32 "
        "{%0,%1,%2,%3}, {%4,%5,%6,%7}, {%8,%9}, {%0,%1,%2,%3};"
        : "+f"(c[0]), "+f"(c[1]), "+f"(c[2]), "+f"(c[3])
        : "r"(a0), "r"(a1), "r"(a2), "r"(a3), "r"(b0), "r"(b1));
}

// -------------------------------------------------------------------------
// Kernel 1: per (b,i):  D[j,f] = e[b,i,j,:] . Wf[f,:]   (tf32 mma.sync)
//           h1[bi,f]  = sum_j selu(D[j,f]+bf[f]) * em[j] * h[b,j,f]
// 256 threads = 8 warps; warp w owns f-block [32w, 32w+32), loops 8 j-tiles
// of 16. B (Wf) frags preloaded to regs; j-reduction via shfl at the end.
// smem strides chosen for conflict-free fragment loads:
//   e_s stride 36  (36 mod 32 = 4  -> bank = 4*r + c, injective)
//   w_s stride 264 (264 mod 32 = 8 -> bank = 8*c + r, injective)
// -------------------------------------------------------------------------
#define ES 36
#define WS 264
#define K1_SMEM ((NA * ES + 32 * WS + NA) * 4)

__global__ __launch_bounds__(256) void efconv_k1(
    const float* __restrict__ hbuf, const float* __restrict__ e,
    const float* __restrict__ edge_mask, const float* __restrict__ Wf,
    const float* __restrict__ bf)
{
    extern __shared__ uint32_t sm1[];
    uint32_t* e_s  = sm1;                 // [128][36] tf32
    uint32_t* w_s  = sm1 + NA * ES;       // [32][264] tf32 (k-major)
    float*    em_s = (float*)(sm1 + NA * ES + 32 * WS); // [128]

    const int tid = threadIdx.x;
    const int w = tid >> 5, l = tid & 31;
    const int r = l >> 2, c = l & 3;
    const int bi = blockIdx.x, b = bi >> 7;

    // ---- stage e[b,i] (128 x 30) as tf32; pad k=30,31 with 0 ----
    const float2* e2 = (const float2*)(e + (size_t)bi * (NA * EF));
    #pragma unroll
    for (int q = 0; q < 8; q++) {
        int idx = tid + q * 256;
        if (idx < 1920) {
            int j = idx / 15, p = idx - j * 15;
            float2 v = e2[idx];
            e_s[j * ES + 2 * p]     = f2tf(v.x);
            e_s[j * ES + 2 * p + 1] = f2tf(v.y);
        }
    }
    if (tid < 128) {
        e_s[tid * ES + 30] = 0; e_s[tid * ES + 31] = 0;
        em_s[tid] = edge_mask[bi * NA + tid];
    }
    // ---- stage Wf transposed (256 x 30 -> [k][f]) as tf32; pad k=30,31 ----
    const float2* w2 = (const float2*)Wf;
    #pragma unroll
    for (int q = 0; q < 15; q++) {
        int idx = tid + q * 256;
        int f = idx / 15, p = idx - f * 15;
        float2 v = w2[idx];
        w_s[(2 * p) * WS + f]     = f2tf(v.x);
        w_s[(2 * p + 1) * WS + f] = f2tf(v.y);
    }
    w_s[30 * WS + tid] = 0; w_s[31 * WS + tid] = 0;
    __syncthreads();

    const int f0 = w * 32;
    // ---- preload B fragments (K=32 -> 4 ks, N=32 -> 4 nb) ----
    uint32_t B[4][4][2];
    #pragma unroll
    for (int ks = 0; ks < 4; ks++)
        #pragma unroll
        for (int nb = 0; nb < 4; nb++) {
            B[ks][nb][0] = w_s[(ks * 8 + c) * WS     + f0 + nb * 8 + r];
            B[ks][nb][1] = w_s[(ks * 8 + c + 4) * WS + f0 + nb * 8 + r];
        }
    float2 bfv[4];
    #pragma unroll
    for (int nb = 0; nb < 4; nb++)
        bfv[nb] = *(const float2*)(bf + f0 + nb * 8 + 2 * c);

    const float* hb = hbuf + (size_t)b * NA * HD;
    float acc[4][2] = {};

    #pragma unroll
    for (int jt = 0; jt < 8; jt++) {
        float C[4][4] = {};
        #pragma unroll
        for (int ks = 0; ks < 4; ks++) {
            uint32_t a0 = e_s[(jt * 16 + r) * ES     + ks * 8 + c];
            uint32_t a1 = e_s[(jt * 16 + r + 8) * ES + ks * 8 + c];
            uint32_t a2 = e_s[(jt * 16 + r) * ES     + ks * 8 + c + 4];
            uint32_t a3 = e_s[(jt * 16 + r + 8) * ES + ks * 8 + c + 4];
            #pragma unroll
            for (int nb = 0; nb < 4; nb++)
                mma_tf32(C[nb], a0, a1, a2, a3, B[ks][nb][0], B[ks][nb][1]);
        }
        const int j0 = jt * 16 + r, j1 = j0 + 8;
        const float em0 = em_s[j0], em1 = em_s[j1];
        #pragma unroll
        for (int nb = 0; nb < 4; nb++) {
            int fc = f0 + nb * 8 + 2 * c;
            float2 h0 = *(const float2*)(hb + (size_t)j0 * HD + fc);
            float2 h1 = *(const float2*)(hb + (size_t)j1 * HD + fc);
            float s0 = selu_f(C[nb][0] + bfv[nb].x) * em0;
            float s1 = selu_f(C[nb][1] + bfv[nb].y) * em0;
            float s2 = selu_f(C[nb][2] + bfv[nb].x) * em1;
            float s3 = selu_f(C[nb][3] + bfv[nb].y) * em1;
            acc[nb][0] = fmaf(s0, h0.x, fmaf(s2, h1.x, acc[nb][0]));
            acc[nb][1] = fmaf(s1, h0.y, fmaf(s3, h1.y, acc[nb][1]));
        }
    }
    // ---- reduce over the 8 row-groups (lanes sharing l&3) ----
    #pragma unroll
    for (int nb = 0; nb < 4; nb++)
        #pragma unroll
        for (int i = 0; i < 2; i++) {
            float v = acc[nb][i];
            v += __shfl_xor_sync(0xffffffffu, v, 4);
            v += __shfl_xor_sync(0xffffffffu, v, 8);
            v += __shfl_xor_sync(0xffffffffu, v, 16);
            acc[nb][i] = v;
        }
    if (l < 4) {
        #pragma unroll
        for (int nb = 0; nb < 4; nb++)
            *(float2*)(g_h1 + (size_t)bi * HD + f0 + nb * 8 + 2 * l) =
                make_float2(acc[nb][0], acc[nb][1]);
    }
}

// -------------------------------------------------------------------------
// Kernel 2: out = selu([h|h1] @ Ww^T + bw) * nm + h
// GEMM M=2048, K=512, N=256. Grid 128 = (32 row-blocks x 4 f-blocks),
// CTA = 64 rows x 64 f, 8 warps: warp = (rt = w&3 -> 16 rows, fh = w>>2 ->
// 32 f). K in 8 chunks of 64, single-buffered smem.
//   z_s stride 68 (mod 32 = 4), w_s stride 72 (mod 32 = 8): conflict-free.
// -------------------------------------------------------------------------
#define ZS 68
#define WS2 72
#define K2_SMEM ((64 * ZS + 64 * WS2) * 4)

__global__ __launch_bounds__(256) void efconv_k2(
    const float* __restrict__ hbuf, const float* __restrict__ node_mask,
    const float* __restrict__ Ww, const float* __restrict__ bw,
    float* __restrict__ out)
{
    extern __shared__ uint32_t sm2[];
    uint32_t* z_s = sm2;             // [64][68] tf32
    uint32_t* w_s = sm2 + 64 * ZS;   // [64][72] tf32 (k-major)

    const int tid = threadIdx.x;
    const int w = tid >> 5, l = tid & 31;
    const int r = l >> 2, c = l & 3;
    const int rb = blockIdx.x >> 2, fb = blockIdx.x & 3;
    const int row0 = rb * 64;
    const int rt = w & 3, fh = w >> 2;
    const int f0w = fb * 64 + fh * 32;

    float C[4][4] = {};

    #pragma unroll 1
    for (int kc = 0; kc < 8; kc++) {
        const float* zsrc = (kc < 4) ? hbuf : g_h1;
        const int cbase = (kc & 3) * 64;
        // stage z chunk: 64 rows x 64 k
        #pragma unroll
        for (int q = 0; q < 4; q++) {
            int idx = tid + q * 256;
            int rr = idx >> 4, kq = idx & 15;
            float4 v = *(const float4*)(zsrc + (size_t)(row0 + rr) * HD + cbase + kq * 4);
            z_s[rr * ZS + kq * 4 + 0] = f2tf(v.x);
            z_s[rr * ZS + kq * 4 + 1] = f2tf(v.y);
            z_s[rr * ZS + kq * 4 + 2] = f2tf(v.z);
            z_s[rr * ZS + kq * 4 + 3] = f2tf(v.w);
        }
        // stage Ww chunk transposed: [k'][f'], f' in [0,64) of this f-block
        #pragma unroll
        for (int q = 0; q < 4; q++) {
            int idx = tid + q * 256;
            int ff = idx >> 4, kq = idx & 15;
            float4 v = *(const float4*)(Ww + (size_t)(fb * 64 + ff) * (2 * HD) + kc * 64 + kq * 4);
            w_s[(kq * 4 + 0) * WS2 + ff] = f2tf(v.x);
            w_s[(kq * 4 + 1) * WS2 + ff] = f2tf(v.y);
            w_s[(kq * 4 + 2) * WS2 + ff] = f2tf(v.z);
            w_s[(kq * 4 + 3) * WS2 + ff] = f2tf(v.w);
        }
        __syncthreads();

        #pragma unroll
        for (int ks = 0; ks < 8; ks++) {
            uint32_t a0 = z_s[(rt * 16 + r) * ZS     + ks * 8 + c];
            uint32_t a1 = z_s[(rt * 16 + r + 8) * ZS + ks * 8 + c];
            uint32_t a2 = z_s[(rt * 16 + r) * ZS     + ks * 8 + c + 4];
            uint32_t a3 = z_s[(rt * 16 + r + 8) * ZS + ks * 8 + c + 4];
            #pragma unroll
            for (int nb = 0; nb < 4; nb++) {
                uint32_t b0 = w_s[(ks * 8 + c) * WS2     + fh * 32 + nb * 8 + r];
                uint32_t b1 = w_s[(ks * 8 + c + 4) * WS2 + fh * 32 + nb * 8 + r];
                mma_tf32(C[nb], a0, a1, a2, a3, b0, b1);
            }
        }
        __syncthreads();
    }

    // ---- epilogue: selu(D + bw) * nm + h ----
    const int rg0 = row0 + rt * 16 + r, rg1 = rg0 + 8;
    const float nm0 = node_mask[rg0], nm1 = node_mask[rg1];
    #pragma unroll
    for (int nb = 0; nb < 4; nb++) {
        int f = f0w + nb * 8 + 2 * c;
        float2 bv = *(const float2*)(bw + f);
        float2 h0 = *(const float2*)(hbuf + (size_t)rg0 * HD + f);
        float2 h1 = *(const float2*)(hbuf + (size_t)rg1 * HD + f);
        float2 o0, o1;
        o0.x = selu_f(C[nb][0] + bv.x) * nm0 + h0.x;
        o0.y = selu_f(C[nb][1] + bv.y) * nm0 + h0.y;
        o1.x = selu_f(C[nb][2] + bv.x) * nm1 + h1.x;
        o1.y = selu_f(C[nb][3] + bv.y) * nm1 + h1.y;
        *(float2*)(out + (size_t)rg0 * HD + f) = o0;
        *(float2*)(out + (size_t)rg1 * HD + f) = o1;
    }
}

extern "C" void kernel_launch(void* const* d_in, const int* in_sizes, int n_in,
                              void* d_out, int out_size)
{
    const float* h   = (const float*)d_in[0];   // (16,128,256)
    const float* e   = (const float*)d_in[1];   // (16,128,128,30)
    const float* nm  = (const float*)d_in[2];   // (16,128,1)
    const float* em  = (const float*)d_in[3];   // (16,128,128,1)
    const float* Wf  = (const float*)d_in[4];   // (256,30)
    const float* bf  = (const float*)d_in[5];   // (256,)
    const float* Ww  = (const float*)d_in[6];   // (256,512)
    const float* bw  = (const float*)d_in[7];   // (256,)
    float* out = (float*)d_out;                  // (16,128,256)

    cudaFuncSetAttribute(efconv_k1, cudaFuncAttributeMaxDynamicSharedMemorySize, K1_SMEM);

    efconv_k1<<<NBATCH * NA, 256, K1_SMEM>>>(h, e, em, Wf, bf);
    efconv_k2<<<128, 256, K2_SMEM>>>(h, nm, Ww, bw, out);
}